// round 1
// baseline (speedup 1.0000x reference)
#include <cuda_runtime.h>

// DEQSolver: Anderson-accelerated ISTA fixed point has closed form
//   z* = soft_threshold(x, lam), and the final ista_step(z*, x) returns
//   soft_threshold(x, lam) again. So the whole thing is one elementwise pass.
//
// out[i] = sign(x[i]) * max(|x[i]| - lam, 0)
//
// lam is a device scalar (d_in[2]); rho (d_in[1]) is mathematically irrelevant
// to the fixed point for rho in (0,1].

__global__ void deq_soft_threshold_kernel(const float4* __restrict__ x,
                                          const float* __restrict__ lam_ptr,
                                          float4* __restrict__ out,
                                          int n4) {
    int i = blockIdx.x * blockDim.x + threadIdx.x;
    if (i >= n4) return;
    const float lam = *lam_ptr;  // L1-cached broadcast after first warp

    float4 v = x[i];
    float4 r;
    r.x = copysignf(fmaxf(fabsf(v.x) - lam, 0.0f), v.x);
    r.y = copysignf(fmaxf(fabsf(v.y) - lam, 0.0f), v.y);
    r.z = copysignf(fmaxf(fabsf(v.z) - lam, 0.0f), v.z);
    r.w = copysignf(fmaxf(fabsf(v.w) - lam, 0.0f), v.w);
    out[i] = r;
}

// Tail handler for sizes not divisible by 4 (defensive; current shape is divisible).
__global__ void deq_soft_threshold_tail(const float* __restrict__ x,
                                        const float* __restrict__ lam_ptr,
                                        float* __restrict__ out,
                                        int start, int n) {
    int i = start + blockIdx.x * blockDim.x + threadIdx.x;
    if (i >= n) return;
    const float lam = *lam_ptr;
    float v = x[i];
    out[i] = copysignf(fmaxf(fabsf(v) - lam, 0.0f), v);
}

extern "C" void kernel_launch(void* const* d_in, const int* in_sizes, int n_in,
                              void* d_out, int out_size) {
    const float* x0  = (const float*)d_in[0];
    // d_in[1] = rho (unused — fixed point is independent of rho)
    const float* lam = (const float*)d_in[2];
    float* out = (float*)d_out;

    int n  = in_sizes[0];          // total elements (8*3*512*512 = 6291456)
    int n4 = n >> 2;               // float4 count
    int tail_start = n4 << 2;

    const int threads = 256;
    if (n4 > 0) {
        int blocks = (n4 + threads - 1) / threads;
        deq_soft_threshold_kernel<<<blocks, threads>>>(
            (const float4*)x0, lam, (float4*)out, n4);
    }
    int tail = n - tail_start;
    if (tail > 0) {
        deq_soft_threshold_tail<<<1, threads>>>(x0, lam, out, tail_start, n);
    }
}

// round 2
// speedup vs baseline: 1.0069x; 1.0069x over previous
#include <cuda_runtime.h>

// DEQSolver closed form: out[i] = sign(x[i]) * max(|x[i]| - lam, 0).
// R2: raise per-thread MLP to 4 (batched independent float4 loads),
// block-tiled so every load is fully coalesced; grid shrinks 6144->1536
// blocks (~1.3 waves), cutting long-scoreboard exposure and wave overhead.

constexpr int UNROLL = 4;
constexpr int THREADS = 256;

__global__ void deq_soft_threshold_u4(const float4* __restrict__ x,
                                      const float* __restrict__ lam_ptr,
                                      float4* __restrict__ out,
                                      int n4) {
    // Block handles UNROLL*THREADS consecutive float4s; thread t touches
    // t, t+THREADS, t+2*THREADS, t+3*THREADS within the block's tile.
    int base = blockIdx.x * (THREADS * UNROLL) + threadIdx.x;

    const float lam = *lam_ptr;

    float4 v[UNROLL];
    bool ok[UNROLL];
#pragma unroll
    for (int j = 0; j < UNROLL; j++) {
        int idx = base + j * THREADS;
        ok[j] = (idx < n4);
        if (ok[j]) v[j] = x[idx];           // 4 independent loads, batched front
    }

#pragma unroll
    for (int j = 0; j < UNROLL; j++) {
        float4 r;
        r.x = copysignf(fmaxf(fabsf(v[j].x) - lam, 0.0f), v[j].x);
        r.y = copysignf(fmaxf(fabsf(v[j].y) - lam, 0.0f), v[j].y);
        r.z = copysignf(fmaxf(fabsf(v[j].z) - lam, 0.0f), v[j].z);
        r.w = copysignf(fmaxf(fabsf(v[j].w) - lam, 0.0f), v[j].w);
        if (ok[j]) out[base + j * THREADS] = r;
    }
}

// Scalar tail (defensive; 6291456 % 4 == 0 so unused for this shape).
__global__ void deq_soft_threshold_tail(const float* __restrict__ x,
                                        const float* __restrict__ lam_ptr,
                                        float* __restrict__ out,
                                        int start, int n) {
    int i = start + blockIdx.x * blockDim.x + threadIdx.x;
    if (i >= n) return;
    const float lam = *lam_ptr;
    float v = x[i];
    out[i] = copysignf(fmaxf(fabsf(v) - lam, 0.0f), v);
}

extern "C" void kernel_launch(void* const* d_in, const int* in_sizes, int n_in,
                              void* d_out, int out_size) {
    const float* x0  = (const float*)d_in[0];
    const float* lam = (const float*)d_in[2];   // d_in[1]=rho is irrelevant
    float* out = (float*)d_out;

    int n  = in_sizes[0];
    int n4 = n >> 2;
    int tail_start = n4 << 2;

    if (n4 > 0) {
        int per_block = THREADS * UNROLL;
        int blocks = (n4 + per_block - 1) / per_block;   // 1536 for this shape
        deq_soft_threshold_u4<<<blocks, THREADS>>>(
            (const float4*)x0, lam, (float4*)out, n4);
    }
    int tail = n - tail_start;
    if (tail > 0) {
        deq_soft_threshold_tail<<<1, THREADS>>>(x0, lam, out, tail_start, n);
    }
}